// round 6
// baseline (speedup 1.0000x reference)
#include <cuda_runtime.h>

// GreedyInvasionMemory: sequential scan, d_k = d_v = 128, seq = 2048.
// Output layout (float32): [costs (2048) | updated 0/1 (2048) | J row-major (128x128)]
//
// Single-CTA persistent kernel, 256 threads. Thread t owns row r = t&127 and
// column half [64*(t>>7), +64) of Sqq, Sqv, J — register-resident as packed
// f32x2 (u64) driven by fma.rn.f32x2.
//
// Matrices kept UNNORMALIZED; decisions scale-invariant; cost divides by l.
// tr(J Sqq J^T), tr(J Sqv), tr(Svv) via EXACT scalar recurrences (no O(d^3)).
// Phase-1 dots run against the PRE-UPDATE matrices (WAR, no RAW stalls);
// phase 4 applies scalar corrections with qk = q.k:
//   ku += qk^2 ;  kp += qk*vv ;  vw += qk*vgd.
// Warp reductions: full SHFL ladders where chains overlap (phase 1);
// TRUNCATED 3-level ladders for the latency-exposed single chains (gg, vw),
// finished by wide adds in the redundant decision phase.
// Decisions computed redundantly in all threads; fp64 master state + cost
// output in thread 0 only (off the critical path).

#define D    128
#define SEQ  2048
#define NT   256
#define CP2  32      // column PAIRS per thread (64 columns)
#define NW   8

typedef unsigned long long u64;

__device__ __forceinline__ u64 ffma2(u64 a, u64 b, u64 c) {
    u64 r; asm("fma.rn.f32x2 %0, %1, %2, %3;" : "=l"(r) : "l"(a), "l"(b), "l"(c));
    return r;
}
__device__ __forceinline__ u64 fmul2(u64 a, u64 b) {
    u64 r; asm("mul.rn.f32x2 %0, %1, %2;" : "=l"(r) : "l"(a), "l"(b));
    return r;
}
__device__ __forceinline__ u64 pack2(float x, float y) {
    u64 r; asm("mov.b64 %0, {%1, %2};" : "=l"(r) : "f"(x), "f"(y));
    return r;
}
__device__ __forceinline__ void unpack2(u64 v, float& x, float& y) {
    asm("mov.b64 {%0, %1}, %2;" : "=f"(x), "=f"(y) : "l"(v));
}
__device__ __forceinline__ float hadd2(u64 v) {
    float x, y; unpack2(v, x, y); return x + y;
}
__device__ __forceinline__ float sum8(const float* p) {
    const float4 a = *(const float4*)p, b = *(const float4*)(p + 4);
    return ((a.x + a.y) + (a.z + a.w)) + ((b.x + b.y) + (b.z + b.w));
}
__device__ __forceinline__ float sum4(const float* p) {
    const float4 a = *(const float4*)p;
    return (a.x + a.y) + (a.z + a.w);
}
__device__ __forceinline__ float sum16(const float* p) {
    return sum8(p) + sum8(p + 8);
}
__device__ __forceinline__ float sum32(const float* p) {
    return sum16(p) + sum16(p + 16);
}

__global__ __launch_bounds__(NT, 1)
void gim_kernel(const float* __restrict__ qg, const float* __restrict__ kg,
                const float* __restrict__ vg, float* __restrict__ out)
{
    __shared__ __align__(16) float sq[2][D], sk[2][D], sv[2][D];
    __shared__ __align__(16) float su[D];
    __shared__ __align__(16) float pu[2 * D], pg[2 * D];
    // parity double-buffered per-warp reduction outputs:
    __shared__ __align__(16) float wA0[2][NW], wA1[2][NW], wA2[2][NW];
    __shared__ __align__(16) float wB0[2][4], wB1[2][4];   // qk, vv
    __shared__ __align__(16) float wB2[2][16];             // gg: 4 partials x 4 warps
    __shared__ __align__(16) float wC[2][32];              // vw: 4 partials x 8 warps
    __shared__ __align__(16) float sTf[2][2];   // fp32 shadows {T, sJ}

    const int tid  = threadIdx.x;
    const int r    = tid & (D - 1);
    const int sub  = tid >> 7;          // 0 or 1
    const int C0   = sub * 64;
    const int warp = tid >> 5;
    const int lane = tid & 31;

    u64 Sqq2[CP2], Sqv2[CP2], Jm2[CP2];
#pragma unroll
    for (int i = 0; i < CP2; i++) { Sqq2[i] = 0ull; Sqv2[i] = 0ull; Jm2[i] = 0ull; }

    // fp64 master state (thread 0 only)
    double Tacc = 0.0, sJ = 0.0, trSvv = 0.0;

    // Prefetch regs live only in threads 128..255 (warps 4-7).
    float rq = 0.f, rk = 0.f, rv = 0.f;
    if (tid >= D) {
        const int j = tid - D;
        sq[0][j] = qg[j]; sk[0][j] = kg[j]; sv[0][j] = vg[j];
        rq = qg[D + j]; rk = kg[D + j]; rv = vg[D + j];
    }
    if (tid == 0) { sTf[0][0] = 0.f; sTf[0][1] = 0.f; sTf[1][0] = 0.f; sTf[1][1] = 0.f; }
    __syncthreads();

    for (int l = 0; l < SEQ; l++) {
        const int par = l & 1, nxt = par ^ 1;
        const float* Q = sq[par];
        const float* K = sk[par];
        const float* V = sv[par];
        const ulonglong2* Q2 = (const ulonglong2*)(Q + C0);
        const ulonglong2* K2 = (const ulonglong2*)(K + C0);
        const ulonglong2* V2 = (const ulonglong2*)(V + C0);

        // ---- Phase 1: dots on OLD matrices (no RAW vs updates), then rank-1
        //      updates Sqq += q q^T, Sqv += q v^T.  (packed f32x2)
        const float qr = Q[r];
        const u64 qr2 = pack2(qr, qr);
        u64 au2 = 0ull, ap2 = 0ull, ag2 = 0ull;
#pragma unroll
        for (int i = 0; i < CP2 / 2; i++) {
            const ulonglong2 q2 = Q2[i], k2 = K2[i], v2 = V2[i];
            const int p = 2 * i;
            au2 = ffma2(Sqq2[p], k2.x, au2);          // old Sqq
            ap2 = ffma2(Sqv2[p], v2.x, ap2);          // old Sqv
            ag2 = ffma2(Jm2[p],  q2.x, ag2);
            Sqq2[p] = ffma2(qr2, q2.x, Sqq2[p]);
            Sqv2[p] = ffma2(qr2, v2.x, Sqv2[p]);
            au2 = ffma2(Sqq2[p + 1], k2.y, au2);      // old (read before write)
            ap2 = ffma2(Sqv2[p + 1], v2.y, ap2);
            ag2 = ffma2(Jm2[p + 1],  q2.y, ag2);
            Sqq2[p + 1] = ffma2(qr2, q2.y, Sqq2[p + 1]);
            Sqv2[p + 1] = ffma2(qr2, v2.y, Sqv2[p + 1]);
        }
        const float au = hadd2(au2), ap = hadd2(ap2), ag = hadd2(ag2);
        pu[sub * D + r] = au;       // partial of u_old = Sqq_old k
        pg[sub * D + r] = ag;       // partial of g = J q
        // In-warp full ladders; the 3 (or 5) chains are independent and
        // overlap, so the tail is ~1 chain of latency.
        {
            const float kr = K[r], vr = V[r];
            float t0 = kr * ap, t1 = kr * au, t2 = vr * ag;
            float t3 = 0.f, t4 = 0.f;
            const bool rowdots = (tid < D);        // warps 0-3 also do qk, vv
            if (rowdots) { t3 = qr * kr; t4 = vr * vr; }
#pragma unroll
            for (int off = 16; off; off >>= 1) {
                t0 += __shfl_down_sync(0xffffffffu, t0, off);
                t1 += __shfl_down_sync(0xffffffffu, t1, off);
                t2 += __shfl_down_sync(0xffffffffu, t2, off);
                t3 += __shfl_down_sync(0xffffffffu, t3, off);
                t4 += __shfl_down_sync(0xffffffffu, t4, off);
            }
            if (lane == 0) {
                wA0[par][warp] = t0; wA1[par][warp] = t1; wA2[par][warp] = t2;
                if (rowdots) { wB0[par][warp] = t3; wB1[par][warp] = t4; }
            }
        }
        __syncthreads();   // A

        // ---- Phase 2 (split): warps 0-3 complete u_old, g; reduce gg with a
        //      TRUNCATED 3-level ladder (lanes 0-3 publish 8-lane partials).
        //      Warps 4-7 do the double-buffer store + LDG prefetch.
        if (tid < D) {
            const float u = pu[tid] + pu[D + tid];
            const float g = pg[tid] + pg[D + tid];
            su[tid] = u;
            float t5 = g * g;
            t5 += __shfl_down_sync(0xffffffffu, t5, 16);
            t5 += __shfl_down_sync(0xffffffffu, t5, 8);
            t5 += __shfl_down_sync(0xffffffffu, t5, 4);
            if (lane < 4) wB2[par][warp * 4 + lane] = t5;
        } else {
            const int j = tid - D;
            sq[nxt][j] = rq; sk[nxt][j] = rk; sv[nxt][j] = rv;
            if (l + 2 < SEQ) {
                const int o = (l + 2) * D + j;
                rq = qg[o]; rk = kg[o]; rv = vg[o];
            }
        }
        __syncthreads();   // B

        // ---- Phase 3: vw_old = v.(J u_old), truncated 3-level ladder.
        {
            u64 aw2 = 0ull;
            const ulonglong2* U2 = (const ulonglong2*)(su + C0);
#pragma unroll
            for (int i = 0; i < CP2 / 2; i++) {
                const ulonglong2 u2 = U2[i];
                aw2 = ffma2(Jm2[2 * i], u2.x, aw2);
                aw2 = ffma2(Jm2[2 * i + 1], u2.y, aw2);
            }
            float t = hadd2(aw2) * V[r];
            t += __shfl_down_sync(0xffffffffu, t, 16);
            t += __shfl_down_sync(0xffffffffu, t, 8);
            t += __shfl_down_sync(0xffffffffu, t, 4);
            if (lane < 4) wC[par][warp * 4 + lane] = t;
        }
        __syncthreads();   // C

        // ---- Phase 4 (ALL threads, redundant, bit-identical): fp32 decision
        //      with scalar corrections for the old-matrix dots.
        float a, b, updf;
        {
            const float kp_r = sum8(wA0[par]);
            const float ku_r = sum8(wA1[par]);
            const float vgd  = sum8(wA2[par]);
            const float vw_r = sum32(wC[par]);
            const float qk   = sum4(wB0[par]);
            const float vv   = sum4(wB1[par]);
            const float gg   = sum16(wB2[par]);

            const float ku = ku_r + qk * qk;      // k^T Sqq' k
            const float kp = kp_r + qk * vv;      // k^T Sqv' v = s_l
            const float vw = vw_r + qk * vgd;     // v^T J Sqq' k = A_Jl

            const float AJJ = sTf[par][0] + gg;   // tr(J Sqq' J^T), old J
            const float sJc = sTf[par][1] + vgd;  // tr(J Sqv'), old J
            const float sl  = kp;
            const float All = vv * ku;
            const float AJl = vw;

            const bool  first  = (l == 0);
            const float AJJs   = (first || AJJ == 0.f) ? 1.f : AJJ;
            const float Alls   = (first || All == 0.f) ? 1.f : All;
            const float denom  = AJJ * All - AJl * AJl;
            const float denoms = (first || denom == 0.f) ? 1.f : denom;

            const float ratio  = sJc / AJJs;
            const float margin = sl - AJl * ratio;
            const float invden = 1.f / denoms;
            const float wf = (All * sJc - AJl * sl) * invden;
            const float wi = (AJJ * sl - AJl * sJc) * invden;
            const float wfc = (wi <= 0.f) ? ratio : ((wf <= 0.f) ? 0.f : wf);
            const float wic = (wi <= 0.f) ? 0.f : ((wf <= 0.f) ? sl / Alls : wi);
            const bool dou = (margin > 0.f);

            if (first)    { a = 0.f; b = 1.f; }   // J = v k^T
            else if (dou) { a = wfc; b = wic; }
            else          { a = 1.f; b = 0.f; }
            updf = (first || dou) ? 1.f : 0.f;

            // Thread 0: exact fp64 master recurrence + outputs (overlaps
            // other warps' phase 5 / next phase 1).
            if (tid == 0) {
                const double qkd = (double)qk, vvd = (double)vv;
                const double kud = (double)ku_r + qkd * qkd;
                const double kpd = (double)kp_r + qkd * vvd;
                const double vwd = (double)vw_r + qkd * (double)vgd;
                const double AJJd = Tacc + (double)gg;
                const double sJcd = sJ + (double)vgd;
                const double Alld = vvd * kud;
                trSvv += vvd;
                const double ad = (double)a, bd = (double)b;
                Tacc = ad * ad * AJJd + 2.0 * ad * bd * vwd + bd * bd * Alld;
                sJ   = ad * sJcd + bd * kpd;
                sTf[nxt][0] = (float)Tacc;
                sTf[nxt][1] = (float)sJ;
                out[l]       = (float)(0.5 * trSvv - sJ + 0.5 * Tacc) / (float)(l + 1);
                out[SEQ + l] = updf;
            }
        }

        // ---- Phase 5: conditional rank-1 J update (registers, f32x2)
        if (updf != 0.f) {
            const u64 a2 = pack2(a, a);
            const float bvr = b * V[r];
            const u64 b2 = pack2(bvr, bvr);
#pragma unroll
            for (int i = 0; i < CP2 / 2; i++) {
                const ulonglong2 k2 = K2[i];
                Jm2[2 * i]     = ffma2(b2, k2.x, fmul2(a2, Jm2[2 * i]));
                Jm2[2 * i + 1] = ffma2(b2, k2.y, fmul2(a2, Jm2[2 * i + 1]));
            }
        }
    }

    // Emit final J [d_v, d_k] row-major.
#pragma unroll
    for (int p = 0; p < CP2; p++) {
        float x, y; unpack2(Jm2[p], x, y);
        out[2 * SEQ + r * D + C0 + 2 * p]     = x;
        out[2 * SEQ + r * D + C0 + 2 * p + 1] = y;
    }
}

extern "C" void kernel_launch(void* const* d_in, const int* in_sizes, int n_in,
                              void* d_out, int out_size)
{
    (void)in_sizes; (void)n_in; (void)out_size;
    gim_kernel<<<1, NT>>>((const float*)d_in[0], (const float*)d_in[1],
                          (const float*)d_in[2], (float*)d_out);
}

// round 10
// speedup vs baseline: 1.2827x; 1.2827x over previous
#include <cuda_runtime.h>

// GreedyInvasionMemory: sequential scan, d_k = d_v = 128, seq = 2048.
// Output layout (float32): [costs (2048) | updated 0/1 (2048) | J row-major (128x128)]
//
// Single-CTA persistent kernel, 256 threads. Thread t owns row r = t&127 and
// column half [64*(t>>7), +64) of Sqq, Sqv, J — register-resident as packed
// f32x2 (u64) driven by fma.rn.f32x2.
//
// Matrices kept UNNORMALIZED; decisions scale-invariant; cost divides by l.
// tr(J Sqq J^T), tr(J Sqv), tr(Svv) via EXACT scalar recurrences (no O(d^3)).
//
// Two latency optimizations vs the measured round-4 baseline:
//  (1) phases 2+3 MERGED: u = Sqq'k never materialized — the J.u loop builds
//      u on the fly from the two pu halves (broadcast LDS + add.rn.f32x2);
//      one barrier removed (3 -> 2 per step).
//  (2) the fp64 master-state update is DEFERRED one step and executed by
//      thread 224 (warp 7) inside the phase-2+3 slack window, removing the
//      ~300-cycle serial fp64 chain from the barrier critical path. It
//      re-derives the step-(l-1) decision bit-identically from the parity
//      buffers, updates fp64 state, publishes the fp32 shadows sTf[par]
//      (read by phase 4 only after barrier B), and writes out[l-1].
// Decisions computed redundantly in all threads (no tail barrier).

#define D    128
#define SEQ  2048
#define NT   256
#define CP2  32      // column PAIRS per thread (64 columns)
#define NW   8

typedef unsigned long long u64;

__device__ __forceinline__ u64 ffma2(u64 a, u64 b, u64 c) {
    u64 r; asm("fma.rn.f32x2 %0, %1, %2, %3;" : "=l"(r) : "l"(a), "l"(b), "l"(c));
    return r;
}
__device__ __forceinline__ u64 fmul2(u64 a, u64 b) {
    u64 r; asm("mul.rn.f32x2 %0, %1, %2;" : "=l"(r) : "l"(a), "l"(b));
    return r;
}
__device__ __forceinline__ u64 faddx2(u64 a, u64 b) {
    u64 r; asm("add.rn.f32x2 %0, %1, %2;" : "=l"(r) : "l"(a), "l"(b));
    return r;
}
__device__ __forceinline__ u64 pack2(float x, float y) {
    u64 r; asm("mov.b64 %0, {%1, %2};" : "=l"(r) : "f"(x), "f"(y));
    return r;
}
__device__ __forceinline__ void unpack2(u64 v, float& x, float& y) {
    asm("mov.b64 {%0, %1}, %2;" : "=f"(x), "=f"(y) : "l"(v));
}
__device__ __forceinline__ float hadd2(u64 v) {
    float x, y; unpack2(v, x, y); return x + y;
}
__device__ __forceinline__ float sum8(const float* p) {
    const float4 a = *(const float4*)p, b = *(const float4*)(p + 4);
    return ((a.x + a.y) + (a.z + a.w)) + ((b.x + b.y) + (b.z + b.w));
}
__device__ __forceinline__ float sum4(const float* p) {
    const float4 a = *(const float4*)p;
    return (a.x + a.y) + (a.z + a.w);
}

__global__ __launch_bounds__(NT, 1)
void gim_kernel(const float* __restrict__ qg, const float* __restrict__ kg,
                const float* __restrict__ vg, float* __restrict__ out)
{
    __shared__ __align__(16) float sq[2][D], sk[2][D], sv[2][D];
    __shared__ __align__(16) float pu[2 * D], pg[2 * D];
    // parity double-buffered per-warp reduction outputs:
    __shared__ __align__(16) float wA0[2][NW], wA1[2][NW], wA2[2][NW], wC[2][NW];
    __shared__ __align__(16) float wB0[2][4], wB1[2][4];   // gg, vv
    __shared__ __align__(16) float sTf[2][2];   // fp32 shadows {T, sJ}

    const int tid  = threadIdx.x;
    const int r    = tid & (D - 1);
    const int sub  = tid >> 7;          // 0 or 1
    const int C0   = sub * 64;
    const int warp = tid >> 5;
    const int lane = tid & 31;

    u64 Sqq2[CP2], Sqv2[CP2], Jm2[CP2];
#pragma unroll
    for (int i = 0; i < CP2; i++) { Sqq2[i] = 0ull; Sqv2[i] = 0ull; Jm2[i] = 0ull; }

    // fp64 master state (meaningful only in thread 224 = warp 7 lane 0)
    double Tacc = 0.0, sJ = 0.0, trSvv = 0.0;

    // Deferred fp64 state update + output for step m (parity mp). Runs in
    // thread 224 during step m+1's phase-2+3 window (and once post-loop).
    // Re-derives the step-m decision bit-identically from the parity buffers.
    auto deferred_update = [&](int m, int mp) {
        const float kp  = sum8(wA0[mp]);
        const float ku  = sum8(wA1[mp]);
        const float vgd = sum8(wA2[mp]);
        const float vw  = sum8(wC[mp]);
        const float gg  = sum4(wB0[mp]);
        const float vv  = sum4(wB1[mp]);

        const float AJJ = sTf[mp][0] + gg;
        const float sJc = sTf[mp][1] + vgd;
        const float sl  = kp;
        const float All = vv * ku;
        const float AJl = vw;

        const bool  first  = (m == 0);
        const float AJJs   = (first || AJJ == 0.f) ? 1.f : AJJ;
        const float Alls   = (first || All == 0.f) ? 1.f : All;
        const float denom  = AJJ * All - AJl * AJl;
        const float denoms = (first || denom == 0.f) ? 1.f : denom;

        const float ratio  = sJc / AJJs;
        const float margin = sl - AJl * ratio;
        const float invden = 1.f / denoms;
        const float wf = (All * sJc - AJl * sl) * invden;
        const float wi = (AJJ * sl - AJl * sJc) * invden;
        const float wfc = (wi <= 0.f) ? ratio : ((wf <= 0.f) ? 0.f : wf);
        const float wic = (wi <= 0.f) ? 0.f : ((wf <= 0.f) ? sl / Alls : wi);
        const bool dou = (margin > 0.f);

        float a, b;
        if (first)    { a = 0.f; b = 1.f; }
        else if (dou) { a = wfc; b = wic; }
        else          { a = 1.f; b = 0.f; }
        const float updf = (first || dou) ? 1.f : 0.f;

        const double AJJd = Tacc + (double)gg;
        const double sJcd = sJ + (double)vgd;
        const double sld  = (double)kp;
        const double Alld = (double)vv * (double)ku;
        const double AJld = (double)vw;
        trSvv += (double)vv;
        const double ad = (double)a, bd = (double)b;
        Tacc = ad * ad * AJJd + 2.0 * ad * bd * AJld + bd * bd * Alld;
        sJ   = ad * sJcd + bd * sld;
        sTf[mp ^ 1][0] = (float)Tacc;
        sTf[mp ^ 1][1] = (float)sJ;
        out[m]       = (float)(0.5 * trSvv - sJ + 0.5 * Tacc) / (float)(m + 1);
        out[SEQ + m] = updf;
    };

    // Prefetch regs live only in threads 128..255 (warps 4-7).
    float rq = 0.f, rk = 0.f, rv = 0.f;
    if (tid >= D) {
        const int j = tid - D;
        sq[0][j] = qg[j]; sk[0][j] = kg[j]; sv[0][j] = vg[j];
        rq = qg[D + j]; rk = kg[D + j]; rv = vg[D + j];
    }
    if (tid == 0) { sTf[0][0] = 0.f; sTf[0][1] = 0.f; sTf[1][0] = 0.f; sTf[1][1] = 0.f; }
    __syncthreads();

    for (int l = 0; l < SEQ; l++) {
        const int par = l & 1, nxt = par ^ 1;
        const float* Q = sq[par];
        const float* K = sk[par];
        const float* V = sv[par];
        const ulonglong2* Q2 = (const ulonglong2*)(Q + C0);
        const ulonglong2* K2 = (const ulonglong2*)(K + C0);
        const ulonglong2* V2 = (const ulonglong2*)(V + C0);

        // ---- Phase 1: rank-1 updates Sqq += q q^T, Sqv += q v^T, fused with
        //      row partials au=(Sqq'k)_r, ap=(Sqv'v)_r, ag=(Jq)_r  (f32x2).
        const float qr = Q[r];
        const u64 qr2 = pack2(qr, qr);
        u64 au2 = 0ull, ap2 = 0ull, ag2 = 0ull;
#pragma unroll
        for (int i = 0; i < CP2 / 2; i++) {
            const ulonglong2 q2 = Q2[i], k2 = K2[i], v2 = V2[i];
            const int p = 2 * i;
            Sqq2[p]     = ffma2(qr2, q2.x, Sqq2[p]);
            au2         = ffma2(Sqq2[p], k2.x, au2);
            Sqv2[p]     = ffma2(qr2, v2.x, Sqv2[p]);
            ap2         = ffma2(Sqv2[p], v2.x, ap2);
            ag2         = ffma2(Jm2[p], q2.x, ag2);
            Sqq2[p + 1] = ffma2(qr2, q2.y, Sqq2[p + 1]);
            au2         = ffma2(Sqq2[p + 1], k2.y, au2);
            Sqv2[p + 1] = ffma2(qr2, v2.y, Sqv2[p + 1]);
            ap2         = ffma2(Sqv2[p + 1], v2.y, ap2);
            ag2         = ffma2(Jm2[p + 1], q2.y, ag2);
        }
        const float au = hadd2(au2), ap = hadd2(ap2), ag = hadd2(ag2);
        pu[sub * D + r] = au;       // partial of u = Sqq' k
        pg[sub * D + r] = ag;       // partial of g = J q
        // in-warp reductions for dots LINEAR in the partials:
        //   kp = k.(Sqv' v) = s_l,  ku = k.(Sqq' k),  vgd = v.(J q)
        {
            const float kr = K[r], vr = V[r];
            float t0 = kr * ap, t1 = kr * au, t2 = vr * ag;
#pragma unroll
            for (int off = 16; off; off >>= 1) {
                t0 += __shfl_down_sync(0xffffffffu, t0, off);
                t1 += __shfl_down_sync(0xffffffffu, t1, off);
                t2 += __shfl_down_sync(0xffffffffu, t2, off);
            }
            if (lane == 0) { wA0[par][warp] = t0; wA1[par][warp] = t1; wA2[par][warp] = t2; }
        }
        __syncthreads();   // A

        // ---- Phase 2+3 merged: vw = v.(J u) with u built ON THE FLY from
        //      the two pu halves — no su, no extra barrier. Warps 0-3 also
        //      reduce gg, vv; warps 4-7 do the double-buffer store + LDG
        //      prefetch, and thread 224 runs the DEFERRED fp64 update for
        //      step l-1 in this window (publishing sTf[par] before barrier B).
        {
            u64 aw2 = 0ull;
            const ulonglong2* PU0 = (const ulonglong2*)(pu + C0);
            const ulonglong2* PU1 = (const ulonglong2*)(pu + D + C0);
#pragma unroll
            for (int i = 0; i < CP2 / 2; i++) {
                const ulonglong2 a0 = PU0[i], a1 = PU1[i];
                const u64 ux = faddx2(a0.x, a1.x);
                const u64 uy = faddx2(a0.y, a1.y);
                aw2 = ffma2(Jm2[2 * i], ux, aw2);
                aw2 = ffma2(Jm2[2 * i + 1], uy, aw2);
            }
            float t = hadd2(aw2) * V[r];
#pragma unroll
            for (int off = 16; off; off >>= 1)
                t += __shfl_down_sync(0xffffffffu, t, off);
            if (lane == 0) wC[par][warp] = t;
        }
        if (tid < D) {
            const float g = pg[tid] + pg[D + tid];
            const float vt = V[tid];
            float t0 = g * g, t1 = vt * vt;
#pragma unroll
            for (int off = 16; off; off >>= 1) {
                t0 += __shfl_down_sync(0xffffffffu, t0, off);
                t1 += __shfl_down_sync(0xffffffffu, t1, off);
            }
            if (lane == 0) { wB0[par][warp] = t0; wB1[par][warp] = t1; }
        } else {
            const int j = tid - D;
            sq[nxt][j] = rq; sk[nxt][j] = rk; sv[nxt][j] = rv;
            if (l + 2 < SEQ) {
                const int o = (l + 2) * D + j;
                rq = qg[o]; rk = kg[o]; rv = vg[o];
            }
            if (tid == 224 && l > 0)
                deferred_update(l - 1, nxt);   // parity of step l-1
        }
        __syncthreads();   // B

        // ---- Phase 4 (ALL threads, redundant, bit-identical): fp32 decision.
        float a, b, updf;
        {
            const float kp  = sum8(wA0[par]);
            const float ku  = sum8(wA1[par]);
            const float vgd = sum8(wA2[par]);
            const float vw  = sum8(wC[par]);
            const float gg  = sum4(wB0[par]);
            const float vv  = sum4(wB1[par]);

            const float AJJ = sTf[par][0] + gg;   // tr(J Sqq' J^T), old J
            const float sJc = sTf[par][1] + vgd;  // tr(J Sqv'), old J
            const float sl  = kp;                 // k^T Sqv' v
            const float All = vv * ku;            // (v.v)(k^T Sqq' k)
            const float AJl = vw;                 // v^T J Sqq' k

            const bool  first  = (l == 0);
            const float AJJs   = (first || AJJ == 0.f) ? 1.f : AJJ;
            const float Alls   = (first || All == 0.f) ? 1.f : All;
            const float denom  = AJJ * All - AJl * AJl;
            const float denoms = (first || denom == 0.f) ? 1.f : denom;

            const float ratio  = sJc / AJJs;
            const float margin = sl - AJl * ratio;
            const float invden = 1.f / denoms;
            const float wf = (All * sJc - AJl * sl) * invden;
            const float wi = (AJJ * sl - AJl * sJc) * invden;
            const float wfc = (wi <= 0.f) ? ratio : ((wf <= 0.f) ? 0.f : wf);
            const float wic = (wi <= 0.f) ? 0.f : ((wf <= 0.f) ? sl / Alls : wi);
            const bool dou = (margin > 0.f);

            if (first)    { a = 0.f; b = 1.f; }   // J = v k^T
            else if (dou) { a = wfc; b = wic; }
            else          { a = 1.f; b = 0.f; }
            updf = (first || dou) ? 1.f : 0.f;
        }

        // ---- Phase 5: conditional rank-1 J update (registers, f32x2)
        if (updf != 0.f) {
            const u64 a2 = pack2(a, a);
            const float bvr = b * V[r];
            const u64 b2 = pack2(bvr, bvr);
#pragma unroll
            for (int i = 0; i < CP2 / 2; i++) {
                const ulonglong2 k2 = K2[i];
                Jm2[2 * i]     = ffma2(b2, k2.x, fmul2(a2, Jm2[2 * i]));
                Jm2[2 * i + 1] = ffma2(b2, k2.y, fmul2(a2, Jm2[2 * i + 1]));
            }
        }
    }

    // Final deferred update for the last step (no step SEQ hosted it).
    if (tid == 224)
        deferred_update(SEQ - 1, (SEQ - 1) & 1);

    // Emit final J [d_v, d_k] row-major.
#pragma unroll
    for (int p = 0; p < CP2; p++) {
        float x, y; unpack2(Jm2[p], x, y);
        out[2 * SEQ + r * D + C0 + 2 * p]     = x;
        out[2 * SEQ + r * D + C0 + 2 * p + 1] = y;
    }
}

extern "C" void kernel_launch(void* const* d_in, const int* in_sizes, int n_in,
                              void* d_out, int out_size)
{
    (void)in_sizes; (void)n_in; (void)out_size;
    gim_kernel<<<1, NT>>>((const float*)d_in[0], (const float*)d_in[1],
                          (const float*)d_in[2], (float*)d_out);
}